// round 3
// baseline (speedup 1.0000x reference)
#include <cuda_runtime.h>

// MaskRCNN RPN: fused per-level proposals + anchor generation + IoU label assignment.
// B=2, levels i=2..6 (h=w=1024>>i), 3 anchors/cell, N=261888 anchors per batch.
//
// Inputs are located by ELEMENT COUNT (all sizes distinct), robust to ordering.
// gt_counts is int64 upstream but delivered as int32 by the harness.
// Output (fp32, concatenated): scores B*N*2 | boxes B*N*4 | anchors B*N*4 | labels B*N*1.

#define B_   2
#define A_   20
#define NTOT 261888

// float-element offsets in d_out
#define OUT_SC 0
#define OUT_BX (B_ * NTOT * 2)                       // 1047552
#define OUT_AN (OUT_BX + B_ * NTOT * 4)              // 3142656
#define OUT_LB (OUT_AN + B_ * NTOT * 4)              // 5237760

struct LvlPtrs {
    const float* cs[5];
    const float* bp[5];
};

__global__ void __launch_bounds__(256)
rpn_fused_kernel(LvlPtrs p,
                 const float* __restrict__ gt,   // B*A*4
                 const int* __restrict__ gtc,    // B (int32 as delivered)
                 float* __restrict__ out)
{
    __shared__ float s_gt[B_ * A_ * 4];
    __shared__ int   s_cnt[B_];

    if (threadIdx.x < B_ * A_ * 4) s_gt[threadIdx.x] = gt[threadIdx.x];
    if (threadIdx.x < B_) {
        int c = gtc[threadIdx.x];
        s_cnt[threadIdx.x] = (c < 0) ? 0 : (c > A_ ? A_ : c);
    }
    __syncthreads();

    int gid = blockIdx.x * blockDim.x + threadIdx.x;
    if (gid >= B_ * NTOT) return;

    int b = gid / NTOT;
    int n = gid - b * NTOT;

    // level ranges: [0,196608) [196608,245760) [245760,258048) [258048,261120) [261120,261888)
    int lvl, offv;
    if      (n < 196608) { lvl = 0; offv = 0;      }
    else if (n < 245760) { lvl = 1; offv = 196608; }
    else if (n < 258048) { lvl = 2; offv = 245760; }
    else if (n < 261120) { lvl = 3; offv = 258048; }
    else                 { lvl = 4; offv = 261120; }

    int log2w  = 8 - lvl;          // w = 256,128,64,32,16
    int log2hw = 2 * log2w;        // hw = w*w
    int hw     = 1 << log2hw;

    int local = n - offv;
    int a   = local >> log2hw;           // anchor type 0..2
    int rem = local & (hw - 1);          // y*w + x
    int y   = rem >> log2w;
    int x   = rem & ((1 << log2w) - 1);

    // anchor geometry
    float s    = (float)(1 << (lvl + 2));          // 2^i
    float half = 0.5f * (s - 1.0f);
    float base = (float)(1 << (lvl + 6));          // 2^(4+i)
    float cy = s * (float)y + half;
    float cx = s * (float)x + half;
    float hh = (a == 2) ? 2.0f * base : base;
    float ww = (a == 0) ? 2.0f * base : base;

    // loads (coalesced along x within each channel plane)
    const float* csp = p.cs[lvl];
    const float* bpp = p.bp[lvl];
    int cbase = (b * 6  + a * 2) * hw + rem;
    int bbase = (b * 12 + a * 4) * hw + rem;
    float c0 = csp[cbase];
    float c1 = csp[cbase + hw];
    float dy = bpp[bbase];
    float dx = bpp[bbase + hw];
    float dh = bpp[bbase + 2 * hw];
    float dw = bpp[bbase + 3 * hw];

    // refined box
    float cyc = cy + dy * hh;
    float cxc = cx + dx * ww;
    float h2  = hh * expf(dh);
    float w2  = ww * expf(dw);

    long long row = (long long)b * NTOT + n;

    *reinterpret_cast<float2*>(out + OUT_SC + row * 2) = make_float2(c0, c1);
    *reinterpret_cast<float4*>(out + OUT_BX + row * 4) =
        make_float4(cyc - 0.5f * h2, cxc - 0.5f * w2, cyc + 0.5f * h2, cxc + 0.5f * w2);
    *reinterpret_cast<float4*>(out + OUT_AN + row * 4) =
        make_float4(cy, cx, hh, ww);

    // label assignment: any(IoU >= 0.5) over valid GT boxes
    float ay1 = cy - 0.5f * hh;
    float ay2 = ay1 + hh;
    float ax1 = cx - 0.5f * ww;
    float ax2 = ax1 + ww;
    float area = hh * ww;

    int cnt = s_cnt[b];
    float lab = 0.0f;
    for (int g = 0; g < cnt; ++g) {
        const float* gb = &s_gt[(b * A_ + g) * 4];
        float gy1 = gb[0], gx1 = gb[1], gy2 = gb[2], gx2 = gb[3];
        float ga = (gy2 - gy1) * (gx2 - gx1);
        float yy1 = fminf(fmaxf(ay1, gy1), gy2);
        float yy2 = fminf(fmaxf(ay2, gy1), gy2);
        float xx1 = fminf(fmaxf(ax1, gx1), gx2);
        float xx2 = fminf(fmaxf(ax2, gx1), gx2);
        float inter = (yy2 - yy1) * (xx2 - xx1);
        float uni = area + ga - inter;
        if (inter / uni >= 0.5f) { lab = 1.0f; break; }
    }
    out[OUT_LB + row] = lab;
}

extern "C" void kernel_launch(void* const* d_in, const int* in_sizes, int n_in,
                              void* d_out, int out_size)
{
    // Assign inputs by unique element count (robust to metadata ordering).
    LvlPtrs p;
    const float* gt = nullptr;
    const int* gtc = nullptr;
    const int cs_sz[5] = {786432, 196608, 49152, 12288, 3072};
    const int bp_sz[5] = {1572864, 393216, 98304, 24576, 6144};

    for (int k = 0; k < n_in; ++k) {
        int sz = in_sizes[k];
        bool matched = false;
        for (int l = 0; l < 5 && !matched; ++l) {
            if (sz == cs_sz[l]) { p.cs[l] = (const float*)d_in[k]; matched = true; }
            else if (sz == bp_sz[l]) { p.bp[l] = (const float*)d_in[k]; matched = true; }
        }
        if (!matched) {
            if (sz == B_ * A_ * 4) gt = (const float*)d_in[k];
            else if (sz == B_)     gtc = (const int*)d_in[k];
            // sz == 1 scalars (img_h/img_w) ignored: fixed at 1024
        }
    }

    float* out = (float*)d_out;
    int total = B_ * NTOT;                 // 523776
    int threads = 256;
    int blocks = (total + threads - 1) / threads;  // 2046
    rpn_fused_kernel<<<blocks, threads>>>(p, gt, gtc, out);
}

// round 4
// speedup vs baseline: 1.4711x; 1.4711x over previous
#include <cuda_runtime.h>

// MaskRCNN RPN fused kernel, ILP-4: each thread handles 4 consecutive anchors
// sharing (batch, level, anchor-type, y). GT loop hoists y-overlap per GT and
// prunes with a conservative margin; exact f32 division only for survivors.

#define B_   2
#define A_   20
#define NTOT 261888

#define OUT_SC 0
#define OUT_BX (B_ * NTOT * 2)
#define OUT_AN (OUT_BX + B_ * NTOT * 4)
#define OUT_LB (OUT_AN + B_ * NTOT * 4)

struct LvlPtrs {
    const float* cs[5];
    const float* bp[5];
};

__global__ void __launch_bounds__(256)
rpn_fused_kernel(LvlPtrs p,
                 const float* __restrict__ gt,   // B*A*4
                 const int* __restrict__ gtc,    // B (int32 as delivered)
                 float* __restrict__ out)
{
    __shared__ float s_gt[B_ * A_ * 4];
    __shared__ float s_ga[B_ * A_];
    __shared__ int   s_cnt[B_];

    int tx = threadIdx.x;
    if (tx < B_ * A_ * 4) s_gt[tx] = gt[tx];
    if (tx < B_) {
        int c = gtc[tx];
        s_cnt[tx] = (c < 0) ? 0 : (c > A_ ? A_ : c);
    }
    __syncthreads();
    if (tx < B_ * A_) {
        const float* gb = &s_gt[tx * 4];
        s_ga[tx] = __fmul_rn(__fsub_rn(gb[2], gb[0]), __fsub_rn(gb[3], gb[1]));
    }
    __syncthreads();

    int t = blockIdx.x * blockDim.x + tx;
    int gid = t * 4;                        // first of 4 anchors
    if (gid >= B_ * NTOT) return;

    int b = (gid >= NTOT) ? 1 : 0;
    int n = gid - b * NTOT;

    int lvl, offv;
    if      (n < 196608) { lvl = 0; offv = 0;      }
    else if (n < 245760) { lvl = 1; offv = 196608; }
    else if (n < 258048) { lvl = 2; offv = 245760; }
    else if (n < 261120) { lvl = 3; offv = 258048; }
    else                 { lvl = 4; offv = 261120; }

    int log2w  = 8 - lvl;
    int log2hw = 2 * log2w;
    int hw     = 1 << log2hw;

    int local = n - offv;
    int a   = local >> log2hw;
    int rem = local & (hw - 1);
    int y   = rem >> log2w;
    int x0  = rem & ((1 << log2w) - 1);     // multiple of 4, same row for all 4

    float s    = (float)(1 << (lvl + 2));
    float half = 0.5f * (s - 1.0f);
    float base = (float)(1 << (lvl + 6));
    float cy  = s * (float)y + half;
    float cx0 = s * (float)x0 + half;
    float hh = (a == 2) ? 2.0f * base : base;
    float ww = (a == 0) ? 2.0f * base : base;

    const float* csp = p.cs[lvl];
    const float* bpp = p.bp[lvl];
    int cbase = (b * 6  + a * 2) * hw + rem;
    int bbase = (b * 12 + a * 4) * hw + rem;

    float4 c0 = *reinterpret_cast<const float4*>(csp + cbase);
    float4 c1 = *reinterpret_cast<const float4*>(csp + cbase + hw);
    float4 dy = *reinterpret_cast<const float4*>(bpp + bbase);
    float4 dx = *reinterpret_cast<const float4*>(bpp + bbase + hw);
    float4 dh = *reinterpret_cast<const float4*>(bpp + bbase + 2 * hw);
    float4 dw = *reinterpret_cast<const float4*>(bpp + bbase + 3 * hw);

    long long row = (long long)b * NTOT + n;

    // scores: interleave (c0,c1) pairs -> 8 floats = 2x float4
    float4* sc = reinterpret_cast<float4*>(out + OUT_SC + row * 2);
    sc[0] = make_float4(c0.x, c1.x, c0.y, c1.y);
    sc[1] = make_float4(c0.z, c1.z, c0.w, c1.w);

    float dyv[4] = {dy.x, dy.y, dy.z, dy.w};
    float dxv[4] = {dx.x, dx.y, dx.z, dx.w};
    float dhv[4] = {dh.x, dh.y, dh.z, dh.w};
    float dwv[4] = {dw.x, dw.y, dw.z, dw.w};

    float4* bx = reinterpret_cast<float4*>(out + OUT_BX + row * 4);
    float4* an = reinterpret_cast<float4*>(out + OUT_AN + row * 4);

#pragma unroll
    for (int j = 0; j < 4; ++j) {
        float cxj = cx0 + (float)j * s;
        float cyc = cy  + dyv[j] * hh;
        float cxc = cxj + dxv[j] * ww;
        float h2  = hh * __expf(dhv[j]);
        float w2  = ww * __expf(dwv[j]);
        bx[j] = make_float4(cyc - 0.5f * h2, cxc - 0.5f * w2,
                            cyc + 0.5f * h2, cxc + 0.5f * w2);
        an[j] = make_float4(cy, cxj, hh, ww);
    }

    // ---- labels: any(IoU >= 0.5) over valid GTs, shared y-overlap ----
    float ay1 = cy - 0.5f * hh;
    float ay2 = ay1 + hh;
    float ax1_0 = cx0 - 0.5f * ww;          // x-edges advance by s per j
    float area = hh * ww;

    int cnt = s_cnt[b];
    int labm = 0;                           // bitmask of positives
    for (int g = 0; g < cnt; ++g) {
        int gi = b * A_ + g;
        const float* gb = &s_gt[gi * 4];
        float gy1 = gb[0], gx1 = gb[1], gy2 = gb[2], gx2 = gb[3];
        float ga = s_ga[gi];

        float yy1 = fminf(fmaxf(ay1, gy1), gy2);
        float yy2 = fminf(fmaxf(ay2, gy1), gy2);
        float oy  = yy2 - yy1;
        float thr = area + ga;
        // conservative prune: max possible inter over x is oy*ww
        if (3.0f * oy * ww < thr * 0.9999f) continue;

#pragma unroll
        for (int j = 0; j < 4; ++j) {
            float a1 = ax1_0 + (float)j * s;
            float a2 = a1 + ww;
            float xx1 = fminf(fmaxf(a1, gx1), gx2);
            float xx2 = fminf(fmaxf(a2, gx1), gx2);
            float inter = __fmul_rn(oy, __fsub_rn(xx2, xx1));
            float uni   = __fsub_rn(thr, inter);
            if (inter / uni >= 0.5f) labm |= (1 << j);
        }
        if (labm == 0xF) break;
    }

    *reinterpret_cast<float4*>(out + OUT_LB + row) =
        make_float4((float)(labm & 1), (float)((labm >> 1) & 1),
                    (float)((labm >> 2) & 1), (float)((labm >> 3) & 1));
}

extern "C" void kernel_launch(void* const* d_in, const int* in_sizes, int n_in,
                              void* d_out, int out_size)
{
    LvlPtrs p;
    const float* gt = nullptr;
    const int* gtc = nullptr;
    const int cs_sz[5] = {786432, 196608, 49152, 12288, 3072};
    const int bp_sz[5] = {1572864, 393216, 98304, 24576, 6144};

    for (int k = 0; k < n_in; ++k) {
        int sz = in_sizes[k];
        bool matched = false;
        for (int l = 0; l < 5 && !matched; ++l) {
            if (sz == cs_sz[l]) { p.cs[l] = (const float*)d_in[k]; matched = true; }
            else if (sz == bp_sz[l]) { p.bp[l] = (const float*)d_in[k]; matched = true; }
        }
        if (!matched) {
            if (sz == B_ * A_ * 4) gt = (const float*)d_in[k];
            else if (sz == B_)     gtc = (const int*)d_in[k];
        }
    }

    float* out = (float*)d_out;
    int threads = 256;
    int total_t = (B_ * NTOT) / 4;                  // 130944
    int blocks = (total_t + threads - 1) / threads; // 512
    rpn_fused_kernel<<<blocks, threads>>>(p, gt, gtc, out);
}